// round 2
// baseline (speedup 1.0000x reference)
#include <cuda_runtime.h>
#include <math.h>

#define H       1024
#define DIN     512
#define T_STEPS 512
#define BATCH   32
#define DT_C    0.1f

#define GRID_R  128
#define BLOCK_R 192
#define HB      8      // H / GRID_R

// ---------------- device scratch (static, allocation-free) ----------------
__device__ float g_Wr[H * H];                 // masked Wr
__device__ float g_Wi[H * H];                 // masked Wi
__device__ float g_Ux[T_STEPS * BATCH * H];   // input projection (64MB)
__device__ float g_ZR[T_STEPS * BATCH * H];   // stored zr per step (64MB)
__device__ float g_zr[BATCH * H];
__device__ float g_zi[BATCH * H];
__device__ float g_act[2 * 3 * H * BATCH];    // [buf][mat][k][b], double-buffered
__device__ unsigned g_bar_count;
__device__ unsigned g_bar_gen;

// ---------------- grid-wide barrier (all CTAs resident) ----------------
__device__ __forceinline__ void grid_barrier() {
    __syncthreads();
    if (threadIdx.x == 0) {
        unsigned gen = atomicAdd(&g_bar_gen, 0u);
        __threadfence();
        unsigned t = atomicAdd(&g_bar_count, 1u);
        if (t == GRID_R - 1) {
            atomicExch(&g_bar_count, 0u);
            __threadfence();
            atomicAdd(&g_bar_gen, 1u);
        } else {
            while (atomicAdd(&g_bar_gen, 0u) == gen) { }
        }
        __threadfence();
    }
    __syncthreads();
}

// ---------------- prep: masked weights ----------------
__global__ void prep_kernel(const float* __restrict__ Wr_w, const float* __restrict__ mask_r,
                            const float* __restrict__ Wi_w, const float* __restrict__ mask_i) {
    int i = blockIdx.x * blockDim.x + threadIdx.x;
    if (i < H * H) {
        g_Wr[i] = Wr_w[i] * (1.0f / (1.0f + expf(-mask_r[i])));
        g_Wi[i] = Wi_w[i] * (1.0f / (1.0f + expf(-mask_i[i])));
    }
}

__global__ void init_kernel() {
    int i = blockIdx.x * blockDim.x + threadIdx.x;
    if (i < BATCH * H) { g_zr[i] = 0.0f; g_zi[i] = 0.0f; }
    if (i < 2 * 3 * H * BATCH) g_act[i] = 0.0f;
}

// ---------------- fp32 GEMM: C[MxN] = A[MxK] * B[NxK]^T + bias[N] ----------------
#define GBM 128
#define GBN 128
#define GBK 8
__global__ __launch_bounds__(256) void sgemm_abt(
    const float* __restrict__ A, const float* __restrict__ B,
    const float* __restrict__ bias, float* __restrict__ C,
    int M, int N, int K) {
    __shared__ float As[GBK][GBM];
    __shared__ float Bs[GBK][GBN];
    const int tid = threadIdx.x;
    const int bm = blockIdx.y * GBM;
    const int bn = blockIdx.x * GBN;
    const int lr = tid >> 1;         // 0..127
    const int lc = (tid & 1) * 4;    // 0 or 4
    const int tx = tid & 15;
    const int ty = tid >> 4;

    float acc[8][8];
#pragma unroll
    for (int i = 0; i < 8; i++)
#pragma unroll
        for (int j = 0; j < 8; j++) acc[i][j] = 0.0f;

    const float* Ap = A + (long)(bm + lr) * K + lc;
    const float* Bp = B + (long)(bn + lr) * K + lc;
    float4 a4 = *(const float4*)Ap;
    float4 b4 = *(const float4*)Bp;

    for (int k0 = 0; k0 < K; k0 += GBK) {
        As[lc + 0][lr] = a4.x; As[lc + 1][lr] = a4.y;
        As[lc + 2][lr] = a4.z; As[lc + 3][lr] = a4.w;
        Bs[lc + 0][lr] = b4.x; Bs[lc + 1][lr] = b4.y;
        Bs[lc + 2][lr] = b4.z; Bs[lc + 3][lr] = b4.w;
        __syncthreads();
        if (k0 + GBK < K) {
            a4 = *(const float4*)(Ap + k0 + GBK);
            b4 = *(const float4*)(Bp + k0 + GBK);
        }
#pragma unroll
        for (int kk = 0; kk < GBK; kk++) {
            float4 a0 = *(const float4*)&As[kk][ty * 8];
            float4 a1 = *(const float4*)&As[kk][ty * 8 + 4];
            float4 c0 = *(const float4*)&Bs[kk][tx * 8];
            float4 c1 = *(const float4*)&Bs[kk][tx * 8 + 4];
            float av[8] = {a0.x, a0.y, a0.z, a0.w, a1.x, a1.y, a1.z, a1.w};
            float bv[8] = {c0.x, c0.y, c0.z, c0.w, c1.x, c1.y, c1.z, c1.w};
#pragma unroll
            for (int i = 0; i < 8; i++)
#pragma unroll
                for (int j = 0; j < 8; j++)
                    acc[i][j] = fmaf(av[i], bv[j], acc[i][j]);
        }
        __syncthreads();
    }

#pragma unroll
    for (int i = 0; i < 8; i++) {
        long row = bm + ty * 8 + i;
#pragma unroll
        for (int j = 0; j < 8; j++) {
            int col = bn + tx * 8 + j;
            C[row * N + col] = acc[i][j] + bias[col];
        }
    }
}

// ---------------- persistent recurrence kernel ----------------
struct RecSmem {
    float W[3][HB][H];          // 96KB: Wr, Wi, Wt rows for this CTA
    float red[BLOCK_R][8];      // k-split partials
    float res[3][HB][BATCH];    // combined matmul results
    float wb[3][HB];            // Wr_b, Wi_b, Wt_b
    float br[HB], bi[HB], tb[HB];
};

#define REC_FMA8(aw, c0, c1)                                        \
    acc[0] = fmaf(c0, aw.x, acc[0]); acc[1] = fmaf(c0, aw.y, acc[1]); \
    acc[2] = fmaf(c0, aw.z, acc[2]); acc[3] = fmaf(c0, aw.w, acc[3]); \
    acc[4] = fmaf(c1, aw.x, acc[4]); acc[5] = fmaf(c1, aw.y, acc[5]); \
    acc[6] = fmaf(c1, aw.z, acc[6]); acc[7] = fmaf(c1, aw.w, acc[7]);

__global__ void __launch_bounds__(BLOCK_R, 1) rec_kernel(
    const float* __restrict__ Wt_w,
    const float* __restrict__ Wr_b, const float* __restrict__ Wi_b,
    const float* __restrict__ Wt_b, const float* __restrict__ b_real,
    const float* __restrict__ b_imag, const float* __restrict__ tau_bias) {
    extern __shared__ char smem_raw[];
    RecSmem& sm = *reinterpret_cast<RecSmem*>(smem_raw);
    const int tid = threadIdx.x;
    const int hbase = blockIdx.x * HB;

    // Load this CTA's weight rows into SMEM once (resident for all 512 steps)
    {
        const float* srcs[3] = {g_Wr + (long)hbase * H, g_Wi + (long)hbase * H,
                                Wt_w + (long)hbase * H};
        const int WN4 = (HB * H) / 4;
        for (int m = 0; m < 3; m++) {
            const float4* s = (const float4*)srcs[m];
            float4* d = (float4*)&sm.W[m][0][0];
            for (int i = tid; i < WN4; i += BLOCK_R) d[i] = s[i];
        }
        if (tid < HB) {
            sm.wb[0][tid] = Wr_b[hbase + tid];
            sm.wb[1][tid] = Wi_b[hbase + tid];
            sm.wb[2][tid] = Wt_b[hbase + tid];
            sm.br[tid] = b_real[hbase + tid];
            sm.bi[tid] = b_imag[hbase + tid];
            sm.tb[tid] = tau_bias[hbase + tid];
        }
    }
    __syncthreads();

    // thread -> (k-split, matrix, h-pair, b-quad)
    const int ks = tid / 96;
    const int r  = tid % 96;
    const int m  = r / 32;
    const int q  = r % 32;
    const int hg = q / 8;
    const int bg = q % 8;
    const int h0 = hg * 2;
    const int b0 = bg * 4;
    const int kbeg = ks * (H / 2);
    const float* wrow0 = &sm.W[m][h0][0];
    const float* wrow1 = &sm.W[m][h0 + 1][0];

    int cur = 0;
    for (int t = 0; t < T_STEPS; t++) {
        const float* actp = g_act + (long)(cur * 3 + m) * H * BATCH;
        float acc[8];
#pragma unroll
        for (int j = 0; j < 8; j++) acc[j] = 0.0f;

#pragma unroll 2
        for (int k = kbeg; k < kbeg + H / 2; k += 4) {
            float4 w0 = *(const float4*)&wrow0[k];
            float4 w1 = *(const float4*)&wrow1[k];
            float4 a0 = __ldg((const float4*)(actp + (k + 0) * BATCH + b0));
            float4 a1 = __ldg((const float4*)(actp + (k + 1) * BATCH + b0));
            float4 a2 = __ldg((const float4*)(actp + (k + 2) * BATCH + b0));
            float4 a3 = __ldg((const float4*)(actp + (k + 3) * BATCH + b0));
            REC_FMA8(a0, w0.x, w1.x)
            REC_FMA8(a1, w0.y, w1.y)
            REC_FMA8(a2, w0.z, w1.z)
            REC_FMA8(a3, w0.w, w1.w)
        }

#pragma unroll
        for (int j = 0; j < 8; j++) sm.red[tid][j] = acc[j];
        __syncthreads();

        if (tid < 96) {
#pragma unroll
            for (int hh = 0; hh < 2; hh++)
#pragma unroll
                for (int bb = 0; bb < 4; bb++) {
                    int j = hh * 4 + bb;
                    sm.res[m][h0 + hh][b0 + bb] = sm.red[tid][j] + sm.red[tid + 96][j];
                }
        }
        __syncthreads();

        // elementwise update for this CTA's (8h x 32b) cells
        const int nxt = cur ^ 1;
        for (int cell = tid; cell < HB * BATCH; cell += BLOCK_R) {
            int b  = cell >> 3;
            int hl = cell & 7;
            int h  = hbase + hl;
            float wr = sm.res[0][hl][b] + sm.wb[0][hl];
            float wi = sm.res[1][hl][b] + sm.wb[1][hl];
            float wt = sm.res[2][hl][b] + sm.wb[2][hl];
            int gi = b * H + h;
            float zr = g_zr[gi], zi = g_zi[gi];
            float ux = g_Ux[((long)t * BATCH + b) * H + h];
            float dr = -zr + wr + ux + sm.br[hl];
            float di = -zi + wi + ux + sm.bi[hl];
            float tau = 1.0f / (1.0f + expf(-wt)) + sm.tb[hl];
            tau = fminf(fmaxf(tau, 0.01f), 1.0f) + 1e-6f;
            dr = fminf(fmaxf(dr / tau, -10.0f), 10.0f);
            di = fminf(fmaxf(di / tau, -10.0f), 10.0f);
            zr = fminf(fmaxf(zr + DT_C * dr, -100.0f), 100.0f);
            zi = fminf(fmaxf(zi + DT_C * di, -100.0f), 100.0f);
            g_zr[gi] = zr;
            g_zi[gi] = zi;
            g_ZR[((long)t * BATCH + b) * H + h] = zr;
            float* ap = g_act + ((long)(nxt * 3) * H + h) * BATCH + b;
            ap[0 * H * BATCH] = tanhf(zr);
            ap[1 * H * BATCH] = tanhf(zi);
            ap[2 * H * BATCH] = sqrtf(zr * zr + zi * zi);
        }

        grid_barrier();
        cur ^= 1;
    }
}

// ---------------- launch ----------------
extern "C" void kernel_launch(void* const* d_in, const int* in_sizes, int n_in,
                              void* d_out, int out_size) {
    const float* x_seq    = (const float*)d_in[0];
    const float* Wr_w     = (const float*)d_in[1];
    const float* Wr_b     = (const float*)d_in[2];
    const float* Wi_w     = (const float*)d_in[3];
    const float* Wi_b     = (const float*)d_in[4];
    const float* U_w      = (const float*)d_in[5];
    const float* U_b      = (const float*)d_in[6];
    const float* Wt_w     = (const float*)d_in[7];
    const float* Wt_b     = (const float*)d_in[8];
    const float* b_real   = (const float*)d_in[9];
    const float* b_imag   = (const float*)d_in[10];
    // mask_r = d_in[11], mask_i = d_in[12] used in prep
    const float* mask_r   = (const float*)d_in[11];
    const float* mask_i   = (const float*)d_in[12];
    const float* tau_bias = (const float*)d_in[13];
    const float* out_w    = (const float*)d_in[14];
    const float* out_b    = (const float*)d_in[15];
    float* y = (float*)d_out;

    float *p_Ux = nullptr, *p_ZR = nullptr;
    cudaGetSymbolAddress((void**)&p_Ux, g_Ux);
    cudaGetSymbolAddress((void**)&p_ZR, g_ZR);

    // 1. masked weights
    prep_kernel<<<(H * H + 255) / 256, 256>>>(Wr_w, mask_r, Wi_w, mask_i);

    // 2. zero state + activations (every call: graph replays must reset)
    init_kernel<<<(2 * 3 * H * BATCH + 255) / 256, 256>>>();

    // 3. Ux = x @ U_w^T + U_b   (M=16384, N=1024, K=512)
    {
        dim3 grid(H / GBN, (T_STEPS * BATCH) / GBM);
        sgemm_abt<<<grid, 256>>>(x_seq, U_w, U_b, p_Ux, T_STEPS * BATCH, H, DIN);
    }

    // 4. persistent recurrence
    {
        int smem = (int)sizeof(RecSmem);
        cudaFuncSetAttribute(rec_kernel, cudaFuncAttributeMaxDynamicSharedMemorySize, smem);
        rec_kernel<<<GRID_R, BLOCK_R, smem>>>(Wt_w, Wr_b, Wi_b, Wt_b, b_real, b_imag, tau_bias);
    }

    // 5. y = ZR @ out_w^T + out_b   (M=16384, N=1024, K=1024)
    {
        dim3 grid(H / GBN, (T_STEPS * BATCH) / GBM);
        sgemm_abt<<<grid, 256>>>(p_ZR, out_w, out_b, y, T_STEPS * BATCH, H, H);
    }
}

// round 3
// speedup vs baseline: 1.9296x; 1.9296x over previous
#include <cuda_runtime.h>
#include <math.h>

#define H       1024
#define DIN     512
#define T_STEPS 512
#define BATCH   32
#define DT_C    0.1f

#define GRID_R  128
#define BLOCK_R 384
#define HB      8      // H / GRID_R

typedef unsigned long long u64;

// ---------------- f32x2 packed math (Blackwell) ----------------
__device__ __forceinline__ u64 fma2(u64 a, u64 b, u64 c) {
    u64 d;
    asm("fma.rn.f32x2 %0, %1, %2, %3;" : "=l"(d) : "l"(a), "l"(b), "l"(c));
    return d;
}
__device__ __forceinline__ u64 add2(u64 a, u64 b) {
    u64 d;
    asm("add.rn.f32x2 %0, %1, %2;" : "=l"(d) : "l"(a), "l"(b));
    return d;
}

// ---------------- device scratch (static, allocation-free) ----------------
__device__ float g_Wr[H * H];                 // masked Wr
__device__ float g_Wi[H * H];                 // masked Wi
__device__ float g_Ux[T_STEPS * BATCH * H];   // input projection
__device__ float g_ZR[T_STEPS * BATCH * H];   // stored zr per step
__device__ float g_zr[BATCH * H];
__device__ float g_zi[BATCH * H];
__device__ float g_act[2 * 3 * H * BATCH];    // [buf][mat][k][b], double-buffered
__device__ unsigned g_bar_count;
__device__ unsigned g_bar_gen;

// ---------------- grid-wide barrier (all CTAs resident) ----------------
// NOTE: the gpu-scope __threadfence() also emits CCTL.IVALL, invalidating this
// SM's L1D each step -> subsequent act reads are guaranteed fresh from L2.
__device__ __forceinline__ void grid_barrier() {
    __syncthreads();
    if (threadIdx.x == 0) {
        unsigned gen = *(volatile unsigned*)&g_bar_gen;
        __threadfence();
        unsigned t = atomicAdd(&g_bar_count, 1u);
        if (t == GRID_R - 1) {
            g_bar_count = 0u;
            __threadfence();
            atomicAdd(&g_bar_gen, 1u);
        } else {
            while (*(volatile unsigned*)&g_bar_gen == gen) { }
        }
        __threadfence();
    }
    __syncthreads();
}

// ---------------- prep: masked weights ----------------
__global__ void prep_kernel(const float* __restrict__ Wr_w, const float* __restrict__ mask_r,
                            const float* __restrict__ Wi_w, const float* __restrict__ mask_i) {
    int i = blockIdx.x * blockDim.x + threadIdx.x;
    if (i < H * H) {
        g_Wr[i] = Wr_w[i] * (1.0f / (1.0f + expf(-mask_r[i])));
        g_Wi[i] = Wi_w[i] * (1.0f / (1.0f + expf(-mask_i[i])));
    }
}

__global__ void init_kernel() {
    int i = blockIdx.x * blockDim.x + threadIdx.x;
    if (i < BATCH * H) { g_zr[i] = 0.0f; g_zi[i] = 0.0f; }
    if (i < 2 * 3 * H * BATCH) g_act[i] = 0.0f;
}

// ---------------- fp32 GEMM: C[MxN] = A[MxK] * B[NxK]^T + bias[N] ----------------
#define GBM 128
#define GBN 128
#define GBK 8
__global__ __launch_bounds__(256) void sgemm_abt(
    const float* __restrict__ A, const float* __restrict__ B,
    const float* __restrict__ bias, float* __restrict__ C,
    int M, int N, int K) {
    __shared__ float As[GBK][GBM];
    __shared__ float Bs[GBK][GBN];
    const int tid = threadIdx.x;
    const int bm = blockIdx.y * GBM;
    const int bn = blockIdx.x * GBN;
    const int lr = tid >> 1;
    const int lc = (tid & 1) * 4;
    const int tx = tid & 15;
    const int ty = tid >> 4;

    float acc[8][8];
#pragma unroll
    for (int i = 0; i < 8; i++)
#pragma unroll
        for (int j = 0; j < 8; j++) acc[i][j] = 0.0f;

    const float* Ap = A + (long)(bm + lr) * K + lc;
    const float* Bp = B + (long)(bn + lr) * K + lc;
    float4 a4 = *(const float4*)Ap;
    float4 b4 = *(const float4*)Bp;

    for (int k0 = 0; k0 < K; k0 += GBK) {
        As[lc + 0][lr] = a4.x; As[lc + 1][lr] = a4.y;
        As[lc + 2][lr] = a4.z; As[lc + 3][lr] = a4.w;
        Bs[lc + 0][lr] = b4.x; Bs[lc + 1][lr] = b4.y;
        Bs[lc + 2][lr] = b4.z; Bs[lc + 3][lr] = b4.w;
        __syncthreads();
        if (k0 + GBK < K) {
            a4 = *(const float4*)(Ap + k0 + GBK);
            b4 = *(const float4*)(Bp + k0 + GBK);
        }
#pragma unroll
        for (int kk = 0; kk < GBK; kk++) {
            float4 a0 = *(const float4*)&As[kk][ty * 8];
            float4 a1 = *(const float4*)&As[kk][ty * 8 + 4];
            float4 c0 = *(const float4*)&Bs[kk][tx * 8];
            float4 c1 = *(const float4*)&Bs[kk][tx * 8 + 4];
            float av[8] = {a0.x, a0.y, a0.z, a0.w, a1.x, a1.y, a1.z, a1.w};
            float bv[8] = {c0.x, c0.y, c0.z, c0.w, c1.x, c1.y, c1.z, c1.w};
#pragma unroll
            for (int i = 0; i < 8; i++)
#pragma unroll
                for (int j = 0; j < 8; j++)
                    acc[i][j] = fmaf(av[i], bv[j], acc[i][j]);
        }
        __syncthreads();
    }

#pragma unroll
    for (int i = 0; i < 8; i++) {
        long row = bm + ty * 8 + i;
#pragma unroll
        for (int j = 0; j < 8; j++) {
            int col = bn + tx * 8 + j;
            C[row * N + col] = acc[i][j] + bias[col];
        }
    }
}

// ---------------- persistent recurrence kernel ----------------
// Thread layout (384 = 3m * 16ks * 8bq):  tid = m*128 + ks*8 + bq
//   warp = one m, 4 consecutive ks (kq=ks&3), 8 bq  -> act LDG.128 hits 4 full lines
// Each thread: all 8 h-rows of its mat  x  4 batch (2 f32x2 pairs), k-range 64 (k = ks + 16*i)
struct RecSmem {
    float2 Wd[3][H][HB];        // duplicated (w,w) pairs, [mat][k][row]  (192KB)
    u64    red[3][4][8][16];    // warp-reduced partials [m][ksgrp][bq][row*2+pair] (12KB)
    float  res[3][HB][BATCH];   // combined matmul results
    float  wb[3][HB];
    float  br[HB], bi[HB], tb[HB];
};

__global__ void __launch_bounds__(BLOCK_R, 1) rec_kernel(
    const float* __restrict__ Wt_w,
    const float* __restrict__ Wr_b, const float* __restrict__ Wi_b,
    const float* __restrict__ Wt_b, const float* __restrict__ b_real,
    const float* __restrict__ b_imag, const float* __restrict__ tau_bias) {
    extern __shared__ char smem_raw[];
    RecSmem& sm = *reinterpret_cast<RecSmem*>(smem_raw);
    const int tid = threadIdx.x;
    const int hbase = blockIdx.x * HB;

    // ---- load + duplicate weights into SMEM (resident for all 512 steps) ----
    for (int idx = tid; idx < 3 * HB * H; idx += BLOCK_R) {
        int m   = idx >> 13;          // /8192
        int rem = idx & 8191;
        int r   = rem >> 10;          // /1024
        int k   = rem & 1023;
        float w;
        if (m == 0)      w = g_Wr[(long)(hbase + r) * H + k];
        else if (m == 1) w = g_Wi[(long)(hbase + r) * H + k];
        else             w = Wt_w[(long)(hbase + r) * H + k];
        sm.Wd[m][k][r] = make_float2(w, w);
    }
    if (tid < HB) {
        sm.wb[0][tid] = Wr_b[hbase + tid];
        sm.wb[1][tid] = Wi_b[hbase + tid];
        sm.wb[2][tid] = Wt_b[hbase + tid];
        sm.br[tid] = b_real[hbase + tid];
        sm.bi[tid] = b_imag[hbase + tid];
        sm.tb[tid] = tau_bias[hbase + tid];
    }
    __syncthreads();

    const int m  = tid >> 7;          // 0..2
    const int r5 = tid & 127;
    const int ks = r5 >> 3;           // 0..15
    const int bq = r5 & 7;            // 0..7
    const int lane = tid & 31;

    const ulonglong2* wbase = (const ulonglong2*)&sm.Wd[m][0][0];

    int cur = 0;
    for (int t = 0; t < T_STEPS; t++) {
        const float* actp = g_act + (long)(cur * 3 + m) * (H * BATCH) + bq * 4;

        u64 acc[16];
#pragma unroll
        for (int j = 0; j < 16; j++) acc[j] = 0ull;

#pragma unroll 4
        for (int i = 0; i < 64; i++) {
            int k = ks + (i << 4);
            ulonglong2 a2 = __ldg((const ulonglong2*)(actp + k * BATCH));
            const ulonglong2* wr = wbase + k * 4;   // 4 x (2 row-pairs)
            ulonglong2 w01 = wr[0];
            ulonglong2 w23 = wr[1];
            ulonglong2 w45 = wr[2];
            ulonglong2 w67 = wr[3];
            acc[0]  = fma2(a2.x, w01.x, acc[0]);  acc[1]  = fma2(a2.y, w01.x, acc[1]);
            acc[2]  = fma2(a2.x, w01.y, acc[2]);  acc[3]  = fma2(a2.y, w01.y, acc[3]);
            acc[4]  = fma2(a2.x, w23.x, acc[4]);  acc[5]  = fma2(a2.y, w23.x, acc[5]);
            acc[6]  = fma2(a2.x, w23.y, acc[6]);  acc[7]  = fma2(a2.y, w23.y, acc[7]);
            acc[8]  = fma2(a2.x, w45.x, acc[8]);  acc[9]  = fma2(a2.y, w45.x, acc[9]);
            acc[10] = fma2(a2.x, w45.y, acc[10]); acc[11] = fma2(a2.y, w45.y, acc[11]);
            acc[12] = fma2(a2.x, w67.x, acc[12]); acc[13] = fma2(a2.y, w67.x, acc[13]);
            acc[14] = fma2(a2.x, w67.y, acc[14]); acc[15] = fma2(a2.y, w67.y, acc[15]);
        }

        // warp butterfly over the 4 kq lanes (lane^8, lane^16)
#pragma unroll
        for (int j = 0; j < 16; j++) {
            u64 o = __shfl_xor_sync(0xffffffffu, acc[j], 8);
            acc[j] = add2(acc[j], o);
            o = __shfl_xor_sync(0xffffffffu, acc[j], 16);
            acc[j] = add2(acc[j], o);
        }
        if ((ks & 3) == 0) {
            int ksg = ks >> 2;
#pragma unroll
            for (int j = 0; j < 16; j++) sm.red[m][ksg][bq][j] = acc[j];
        }
        __syncthreads();

        // combine 4 k-groups: 384 combos, one per thread
        {
            int m2  = tid >> 7;
            int rem = tid & 127;
            int bq2 = rem >> 4;
            int j   = rem & 15;
            float2 s = *(float2*)&sm.red[m2][0][bq2][j];
            float2 p1 = *(float2*)&sm.red[m2][1][bq2][j];
            float2 p2 = *(float2*)&sm.red[m2][2][bq2][j];
            float2 p3 = *(float2*)&sm.red[m2][3][bq2][j];
            s.x += p1.x + p2.x + p3.x;
            s.y += p1.y + p2.y + p3.y;
            int row = j >> 1;
            int b0  = bq2 * 4 + (j & 1) * 2;
            *(float2*)&sm.res[m2][row][b0] = s;
        }
        __syncthreads();

        // elementwise update for this CTA's (8h x 32b) cells
        const int nxt = cur ^ 1;
        if (tid < HB * BATCH) {
            int b  = tid >> 3;
            int hl = tid & 7;
            int h  = hbase + hl;
            float wr = sm.res[0][hl][b] + sm.wb[0][hl];
            float wi = sm.res[1][hl][b] + sm.wb[1][hl];
            float wt = sm.res[2][hl][b] + sm.wb[2][hl];
            int gi = b * H + h;
            float zr = g_zr[gi], zi = g_zi[gi];
            float ux = g_Ux[((long)t * BATCH + b) * H + h];
            float dr = -zr + wr + ux + sm.br[hl];
            float di = -zi + wi + ux + sm.bi[hl];
            float tau = 1.0f / (1.0f + expf(-wt)) + sm.tb[hl];
            tau = fminf(fmaxf(tau, 0.01f), 1.0f) + 1e-6f;
            dr = fminf(fmaxf(dr / tau, -10.0f), 10.0f);
            di = fminf(fmaxf(di / tau, -10.0f), 10.0f);
            zr = fminf(fmaxf(zr + DT_C * dr, -100.0f), 100.0f);
            zi = fminf(fmaxf(zi + DT_C * di, -100.0f), 100.0f);
            g_zr[gi] = zr;
            g_zi[gi] = zi;
            g_ZR[((long)t * BATCH + b) * H + h] = zr;
            float* ap = g_act + ((long)(nxt * 3) * H + h) * BATCH + b;
            ap[0 * H * BATCH] = tanhf(zr);
            ap[1 * H * BATCH] = tanhf(zi);
            ap[2 * H * BATCH] = sqrtf(zr * zr + zi * zi);
        }

        grid_barrier();
        cur ^= 1;
    }
}

// ---------------- launch ----------------
extern "C" void kernel_launch(void* const* d_in, const int* in_sizes, int n_in,
                              void* d_out, int out_size) {
    const float* x_seq    = (const float*)d_in[0];
    const float* Wr_w     = (const float*)d_in[1];
    const float* Wr_b     = (const float*)d_in[2];
    const float* Wi_w     = (const float*)d_in[3];
    const float* Wi_b     = (const float*)d_in[4];
    const float* U_w      = (const float*)d_in[5];
    const float* U_b      = (const float*)d_in[6];
    const float* Wt_w     = (const float*)d_in[7];
    const float* Wt_b     = (const float*)d_in[8];
    const float* b_real   = (const float*)d_in[9];
    const float* b_imag   = (const float*)d_in[10];
    const float* mask_r   = (const float*)d_in[11];
    const float* mask_i   = (const float*)d_in[12];
    const float* tau_bias = (const float*)d_in[13];
    const float* out_w    = (const float*)d_in[14];
    const float* out_b    = (const float*)d_in[15];
    float* y = (float*)d_out;

    float *p_Ux = nullptr, *p_ZR = nullptr;
    cudaGetSymbolAddress((void**)&p_Ux, g_Ux);
    cudaGetSymbolAddress((void**)&p_ZR, g_ZR);

    // 1. masked weights
    prep_kernel<<<(H * H + 255) / 256, 256>>>(Wr_w, mask_r, Wi_w, mask_i);

    // 2. zero state + activations (graph replays must reset)
    init_kernel<<<(2 * 3 * H * BATCH + 255) / 256, 256>>>();

    // 3. Ux = x @ U_w^T + U_b
    {
        dim3 grid(H / GBN, (T_STEPS * BATCH) / GBM);
        sgemm_abt<<<grid, 256>>>(x_seq, U_w, U_b, p_Ux, T_STEPS * BATCH, H, DIN);
    }

    // 4. persistent recurrence
    {
        int smem = (int)sizeof(RecSmem);
        cudaFuncSetAttribute(rec_kernel, cudaFuncAttributeMaxDynamicSharedMemorySize, smem);
        rec_kernel<<<GRID_R, BLOCK_R, smem>>>(Wt_w, Wr_b, Wi_b, Wt_b, b_real, b_imag, tau_bias);
    }

    // 5. y = ZR @ out_w^T + out_b
    {
        dim3 grid(H / GBN, (T_STEPS * BATCH) / GBM);
        sgemm_abt<<<grid, 256>>>(p_ZR, out_w, out_b, y, T_STEPS * BATCH, H, H);
    }
}

// round 4
// speedup vs baseline: 2.0563x; 1.0657x over previous
#include <cuda_runtime.h>
#include <math.h>

#define H       1024
#define DIN     512
#define T_STEPS 512
#define BATCH   32
#define DT_C    0.1f

#define GRID_R  128
#define BLOCK_R 768
#define HB      8      // H / GRID_R

typedef unsigned long long u64;

// ---------------- f32x2 packed math (Blackwell) ----------------
__device__ __forceinline__ u64 fma2(u64 a, u64 b, u64 c) {
    u64 d;
    asm("fma.rn.f32x2 %0, %1, %2, %3;" : "=l"(d) : "l"(a), "l"(b), "l"(c));
    return d;
}
__device__ __forceinline__ u64 add2(u64 a, u64 b) {
    u64 d;
    asm("add.rn.f32x2 %0, %1, %2;" : "=l"(d) : "l"(a), "l"(b));
    return d;
}
__device__ __forceinline__ u64 dup2(float a) {
    u64 d;
    asm("mov.b64 %0, {%1, %1};" : "=l"(d) : "f"(a));
    return d;
}

// ---------------- device scratch (static, allocation-free) ----------------
__device__ float g_Wr[H * H];
__device__ float g_Wi[H * H];
__device__ float g_Ux[T_STEPS * BATCH * H];
__device__ float g_ZR[T_STEPS * BATCH * H];
__device__ float g_act[2 * 3 * H * BATCH];    // [buf][mat][k][b]
__device__ unsigned g_bar_count;
__device__ unsigned g_bar_gen;

// ---------------- grid-wide barrier (all CTAs resident) ----------------
__device__ __forceinline__ void grid_barrier() {
    __syncthreads();
    if (threadIdx.x == 0) {
        unsigned gen = *(volatile unsigned*)&g_bar_gen;
        __threadfence();
        unsigned t = atomicAdd(&g_bar_count, 1u);
        if (t == GRID_R - 1) {
            g_bar_count = 0u;
            __threadfence();
            atomicAdd(&g_bar_gen, 1u);
        } else {
            while (*(volatile unsigned*)&g_bar_gen == gen) { }
        }
        __threadfence();
    }
    __syncthreads();
}

// ---------------- prep: masked weights ----------------
__global__ void prep_kernel(const float* __restrict__ Wr_w, const float* __restrict__ mask_r,
                            const float* __restrict__ Wi_w, const float* __restrict__ mask_i) {
    int i = blockIdx.x * blockDim.x + threadIdx.x;
    if (i < H * H) {
        g_Wr[i] = Wr_w[i] * (1.0f / (1.0f + expf(-mask_r[i])));
        g_Wi[i] = Wi_w[i] * (1.0f / (1.0f + expf(-mask_i[i])));
    }
}

__global__ void init_kernel() {
    int i = blockIdx.x * blockDim.x + threadIdx.x;
    if (i < 2 * 3 * H * BATCH) g_act[i] = 0.0f;
}

// ---------------- fp32 GEMM (f32x2 inner): C = A * B^T + bias ----------------
#define GBM 128
#define GBN 128
#define GBK 8
__global__ __launch_bounds__(256) void sgemm_abt(
    const float* __restrict__ A, const float* __restrict__ B,
    const float* __restrict__ bias, float* __restrict__ C,
    int M, int N, int K) {
    __shared__ float As[GBK][GBM];
    __shared__ float Bs[GBK][GBN];
    const int tid = threadIdx.x;
    const int bm = blockIdx.y * GBM;
    const int bn = blockIdx.x * GBN;
    const int lr = tid >> 1;
    const int lc = (tid & 1) * 4;
    const int tx = tid & 15;
    const int ty = tid >> 4;

    u64 acc2[8][4];
#pragma unroll
    for (int i = 0; i < 8; i++)
#pragma unroll
        for (int j = 0; j < 4; j++) acc2[i][j] = 0ull;

    const float* Ap = A + (long)(bm + lr) * K + lc;
    const float* Bp = B + (long)(bn + lr) * K + lc;
    float4 a4 = *(const float4*)Ap;
    float4 b4 = *(const float4*)Bp;

    for (int k0 = 0; k0 < K; k0 += GBK) {
        As[lc + 0][lr] = a4.x; As[lc + 1][lr] = a4.y;
        As[lc + 2][lr] = a4.z; As[lc + 3][lr] = a4.w;
        Bs[lc + 0][lr] = b4.x; Bs[lc + 1][lr] = b4.y;
        Bs[lc + 2][lr] = b4.z; Bs[lc + 3][lr] = b4.w;
        __syncthreads();
        if (k0 + GBK < K) {
            a4 = *(const float4*)(Ap + k0 + GBK);
            b4 = *(const float4*)(Bp + k0 + GBK);
        }
#pragma unroll
        for (int kk = 0; kk < GBK; kk++) {
            float4 a0 = *(const float4*)&As[kk][ty * 8];
            float4 a1 = *(const float4*)&As[kk][ty * 8 + 4];
            ulonglong2 bp0 = *(const ulonglong2*)&Bs[kk][tx * 8];
            ulonglong2 bp1 = *(const ulonglong2*)&Bs[kk][tx * 8 + 4];
            u64 ad[8] = {dup2(a0.x), dup2(a0.y), dup2(a0.z), dup2(a0.w),
                         dup2(a1.x), dup2(a1.y), dup2(a1.z), dup2(a1.w)};
#pragma unroll
            for (int i = 0; i < 8; i++) {
                acc2[i][0] = fma2(ad[i], bp0.x, acc2[i][0]);
                acc2[i][1] = fma2(ad[i], bp0.y, acc2[i][1]);
                acc2[i][2] = fma2(ad[i], bp1.x, acc2[i][2]);
                acc2[i][3] = fma2(ad[i], bp1.y, acc2[i][3]);
            }
        }
        __syncthreads();
    }

#pragma unroll
    for (int i = 0; i < 8; i++) {
        long row = bm + ty * 8 + i;
#pragma unroll
        for (int j = 0; j < 4; j++) {
            int col = bn + tx * 8 + j * 2;
            float2 v = *(float2*)&acc2[i][j];
            v.x += bias[col];
            v.y += bias[col + 1];
            *(float2*)&C[row * N + col] = v;
        }
    }
}

// ---------------- persistent recurrence kernel ----------------
// 768 threads = 3 mats x 32 ks x 8 bq; warp = 4 ks x 8 bq.
// Each thread: 8 h-rows (4 f32x2 row... pairs via dup-weights) x 4 batch, 32 k-iters.
struct RecSmem {
    float2 Wd[3][H][HB];        // duplicated (w,w) pairs, [mat][k][row]  (192KB)
    u64    red[3][8][8][16];    // warp-reduced partials [m][ksgrp][bq][j] (24KB)
    float  res[3][HB][BATCH];
    float  wb[3][HB];
    float  br[HB], bi[HB], tb[HB];
};

__global__ void __launch_bounds__(BLOCK_R, 1) rec_kernel(
    const float* __restrict__ Wt_w,
    const float* __restrict__ Wr_b, const float* __restrict__ Wi_b,
    const float* __restrict__ Wt_b, const float* __restrict__ b_real,
    const float* __restrict__ b_imag, const float* __restrict__ tau_bias) {
    extern __shared__ char smem_raw[];
    RecSmem& sm = *reinterpret_cast<RecSmem*>(smem_raw);
    const int tid = threadIdx.x;
    const int hbase = blockIdx.x * HB;

    // ---- load + duplicate weights into SMEM (resident for all 512 steps) ----
    for (int idx = tid; idx < 3 * HB * H; idx += BLOCK_R) {
        int m   = idx >> 13;
        int rem = idx & 8191;
        int r   = rem >> 10;
        int k   = rem & 1023;
        float w;
        if (m == 0)      w = g_Wr[(long)(hbase + r) * H + k];
        else if (m == 1) w = g_Wi[(long)(hbase + r) * H + k];
        else             w = Wt_w[(long)(hbase + r) * H + k];
        sm.Wd[m][k][r] = make_float2(w, w);
    }
    if (tid < HB) {
        sm.wb[0][tid] = Wr_b[hbase + tid];
        sm.wb[1][tid] = Wi_b[hbase + tid];
        sm.wb[2][tid] = Wt_b[hbase + tid];
        sm.br[tid] = b_real[hbase + tid];
        sm.bi[tid] = b_imag[hbase + tid];
        sm.tb[tid] = tau_bias[hbase + tid];
    }
    __syncthreads();

    const int m  = tid >> 8;          // 0..2
    const int r5 = tid & 255;
    const int ks = r5 >> 3;           // 0..31
    const int bq = r5 & 7;            // 0..7

    const ulonglong2* wbase = (const ulonglong2*)&sm.Wd[m][0][0];

    // cell state held in registers for the whole sequence (CTA-private)
    const int cb  = tid >> 3;         // batch (tid<256)
    const int chl = tid & 7;          // local h
    float zr = 0.0f, zi = 0.0f;

    int cur = 0;
    for (int t = 0; t < T_STEPS; t++) {
        // prefetch Ux for the epilogue (overlaps with matmul)
        float ux = 0.0f;
        if (tid < HB * BATCH)
            ux = __ldg(&g_Ux[((long)t * BATCH + cb) * H + hbase + chl]);

        const float* actp = g_act + (long)(cur * 3 + m) * (H * BATCH) + bq * 4;

        u64 acc[16];
#pragma unroll
        for (int j = 0; j < 16; j++) acc[j] = 0ull;

#pragma unroll 4
        for (int i = 0; i < 32; i++) {
            int k = ks + (i << 5);
            ulonglong2 a2 = __ldg((const ulonglong2*)(actp + k * BATCH));
            const ulonglong2* wr = wbase + k * 4;
            ulonglong2 w01 = wr[0];
            ulonglong2 w23 = wr[1];
            ulonglong2 w45 = wr[2];
            ulonglong2 w67 = wr[3];
            acc[0]  = fma2(a2.x, w01.x, acc[0]);  acc[1]  = fma2(a2.y, w01.x, acc[1]);
            acc[2]  = fma2(a2.x, w01.y, acc[2]);  acc[3]  = fma2(a2.y, w01.y, acc[3]);
            acc[4]  = fma2(a2.x, w23.x, acc[4]);  acc[5]  = fma2(a2.y, w23.x, acc[5]);
            acc[6]  = fma2(a2.x, w23.y, acc[6]);  acc[7]  = fma2(a2.y, w23.y, acc[7]);
            acc[8]  = fma2(a2.x, w45.x, acc[8]);  acc[9]  = fma2(a2.y, w45.x, acc[9]);
            acc[10] = fma2(a2.x, w45.y, acc[10]); acc[11] = fma2(a2.y, w45.y, acc[11]);
            acc[12] = fma2(a2.x, w67.x, acc[12]); acc[13] = fma2(a2.y, w67.x, acc[13]);
            acc[14] = fma2(a2.x, w67.y, acc[14]); acc[15] = fma2(a2.y, w67.y, acc[15]);
        }

        // warp butterfly over the 4 kq lanes
#pragma unroll
        for (int j = 0; j < 16; j++) {
            u64 o = __shfl_xor_sync(0xffffffffu, acc[j], 8);
            acc[j] = add2(acc[j], o);
            o = __shfl_xor_sync(0xffffffffu, acc[j], 16);
            acc[j] = add2(acc[j], o);
        }
        if ((ks & 3) == 0) {
            int ksg = ks >> 2;
#pragma unroll
            for (int j = 0; j < 16; j++) sm.red[m][ksg][bq][j] = acc[j];
        }
        __syncthreads();

        // combine 8 k-groups: 384 combos, one per thread
        if (tid < 384) {
            int m2  = tid >> 7;
            int rem = tid & 127;
            int bq2 = rem >> 4;
            int j   = rem & 15;
            float2 s = *(float2*)&sm.red[m2][0][bq2][j];
#pragma unroll
            for (int g = 1; g < 8; g++) {
                float2 p = *(float2*)&sm.red[m2][g][bq2][j];
                s.x += p.x; s.y += p.y;
            }
            int row = j >> 1;
            int b0  = bq2 * 4 + (j & 1) * 2;
            *(float2*)&sm.res[m2][row][b0] = s;
        }
        __syncthreads();

        // elementwise update (state lives in registers)
        const int nxt = cur ^ 1;
        if (tid < HB * BATCH) {
            int b  = cb;
            int hl = chl;
            int h  = hbase + hl;
            float wr = sm.res[0][hl][b] + sm.wb[0][hl];
            float wi = sm.res[1][hl][b] + sm.wb[1][hl];
            float wt = sm.res[2][hl][b] + sm.wb[2][hl];
            float dr = -zr + wr + ux + sm.br[hl];
            float di = -zi + wi + ux + sm.bi[hl];
            float tau = 1.0f / (1.0f + expf(-wt)) + sm.tb[hl];
            tau = fminf(fmaxf(tau, 0.01f), 1.0f) + 1e-6f;
            dr = fminf(fmaxf(dr / tau, -10.0f), 10.0f);
            di = fminf(fmaxf(di / tau, -10.0f), 10.0f);
            zr = fminf(fmaxf(zr + DT_C * dr, -100.0f), 100.0f);
            zi = fminf(fmaxf(zi + DT_C * di, -100.0f), 100.0f);
            g_ZR[((long)t * BATCH + b) * H + h] = zr;
            float* ap = g_act + ((long)(nxt * 3) * H + h) * BATCH + b;
            ap[0 * H * BATCH] = tanhf(zr);
            ap[1 * H * BATCH] = tanhf(zi);
            ap[2 * H * BATCH] = sqrtf(zr * zr + zi * zi);
        }

        grid_barrier();
        cur ^= 1;
    }
}

// ---------------- launch ----------------
extern "C" void kernel_launch(void* const* d_in, const int* in_sizes, int n_in,
                              void* d_out, int out_size) {
    const float* x_seq    = (const float*)d_in[0];
    const float* Wr_w     = (const float*)d_in[1];
    const float* Wr_b     = (const float*)d_in[2];
    const float* Wi_w     = (const float*)d_in[3];
    const float* Wi_b     = (const float*)d_in[4];
    const float* U_w      = (const float*)d_in[5];
    const float* U_b      = (const float*)d_in[6];
    const float* Wt_w     = (const float*)d_in[7];
    const float* Wt_b     = (const float*)d_in[8];
    const float* b_real   = (const float*)d_in[9];
    const float* b_imag   = (const float*)d_in[10];
    const float* mask_r   = (const float*)d_in[11];
    const float* mask_i   = (const float*)d_in[12];
    const float* tau_bias = (const float*)d_in[13];
    const float* out_w    = (const float*)d_in[14];
    const float* out_b    = (const float*)d_in[15];
    float* y = (float*)d_out;

    float *p_Ux = nullptr, *p_ZR = nullptr;
    cudaGetSymbolAddress((void**)&p_Ux, g_Ux);
    cudaGetSymbolAddress((void**)&p_ZR, g_ZR);

    prep_kernel<<<(H * H + 255) / 256, 256>>>(Wr_w, mask_r, Wi_w, mask_i);
    init_kernel<<<(2 * 3 * H * BATCH + 255) / 256, 256>>>();

    {
        dim3 grid(H / GBN, (T_STEPS * BATCH) / GBM);
        sgemm_abt<<<grid, 256>>>(x_seq, U_w, U_b, p_Ux, T_STEPS * BATCH, H, DIN);
    }

    {
        int smem = (int)sizeof(RecSmem);
        cudaFuncSetAttribute(rec_kernel, cudaFuncAttributeMaxDynamicSharedMemorySize, smem);
        rec_kernel<<<GRID_R, BLOCK_R, smem>>>(Wt_w, Wr_b, Wi_b, Wt_b, b_real, b_imag, tau_bias);
    }

    {
        dim3 grid(H / GBN, (T_STEPS * BATCH) / GBM);
        sgemm_abt<<<grid, 256>>>(p_ZR, out_w, out_b, y, T_STEPS * BATCH, H, H);
    }
}

// round 5
// speedup vs baseline: 2.2420x; 1.0903x over previous
#include <cuda_runtime.h>
#include <math.h>

#define H       1024
#define DIN     512
#define T_STEPS 512
#define BATCH   32
#define DT_C    0.1f

#define GRID_R  128
#define BLOCK_R 768
#define HB      8      // H / GRID_R

typedef unsigned long long u64;

// ---------------- f32x2 packed math (Blackwell) ----------------
__device__ __forceinline__ u64 fma2(u64 a, u64 b, u64 c) {
    u64 d;
    asm("fma.rn.f32x2 %0, %1, %2, %3;" : "=l"(d) : "l"(a), "l"(b), "l"(c));
    return d;
}
__device__ __forceinline__ u64 add2(u64 a, u64 b) {
    u64 d;
    asm("add.rn.f32x2 %0, %1, %2;" : "=l"(d) : "l"(a), "l"(b));
    return d;
}
__device__ __forceinline__ u64 dup2(float a) {
    u64 d;
    asm("mov.b64 %0, {%1, %1};" : "=l"(d) : "f"(a));
    return d;
}

// ---------------- device scratch (static, allocation-free) ----------------
__device__ float g_Wr[H * H];
__device__ float g_Wi[H * H];
__device__ float g_Ux[T_STEPS * BATCH * H];
__device__ float g_ZR[T_STEPS * BATCH * H];
__device__ float g_act[2 * 3 * H * BATCH];    // [buf][mat][k][b]
__device__ unsigned g_bar_count;
__device__ unsigned g_bar_gen;

// ---------------- grid-wide barrier (all CTAs resident) ----------------
__device__ __forceinline__ void grid_barrier() {
    __syncthreads();
    if (threadIdx.x == 0) {
        unsigned gen = *(volatile unsigned*)&g_bar_gen;
        __threadfence();
        unsigned t = atomicAdd(&g_bar_count, 1u);
        if (t == GRID_R - 1) {
            g_bar_count = 0u;
            __threadfence();
            atomicAdd(&g_bar_gen, 1u);
        } else {
            while (*(volatile unsigned*)&g_bar_gen == gen) { }
        }
        __threadfence();
    }
    __syncthreads();
}

// ---------------- prep: masked weights ----------------
__global__ void prep_kernel(const float* __restrict__ Wr_w, const float* __restrict__ mask_r,
                            const float* __restrict__ Wi_w, const float* __restrict__ mask_i) {
    int i = blockIdx.x * blockDim.x + threadIdx.x;
    if (i < H * H) {
        g_Wr[i] = Wr_w[i] * (1.0f / (1.0f + expf(-mask_r[i])));
        g_Wi[i] = Wi_w[i] * (1.0f / (1.0f + expf(-mask_i[i])));
    }
}

__global__ void init_kernel() {
    int i = blockIdx.x * blockDim.x + threadIdx.x;
    if (i < 2 * 3 * H * BATCH) g_act[i] = 0.0f;
}

// ---------------- fp32 GEMM (f32x2 inner): C = A * B^T + bias ----------------
#define GBM 128
#define GBN 128
#define GBK 8
__global__ __launch_bounds__(256) void sgemm_abt(
    const float* __restrict__ A, const float* __restrict__ B,
    const float* __restrict__ bias, float* __restrict__ C,
    int M, int N, int K) {
    __shared__ float As[GBK][GBM];
    __shared__ float Bs[GBK][GBN];
    const int tid = threadIdx.x;
    const int bm = blockIdx.y * GBM;
    const int bn = blockIdx.x * GBN;
    const int lr = tid >> 1;
    const int lc = (tid & 1) * 4;
    const int tx = tid & 15;
    const int ty = tid >> 4;

    u64 acc2[8][4];
#pragma unroll
    for (int i = 0; i < 8; i++)
#pragma unroll
        for (int j = 0; j < 4; j++) acc2[i][j] = 0ull;

    const float* Ap = A + (long)(bm + lr) * K + lc;
    const float* Bp = B + (long)(bn + lr) * K + lc;
    float4 a4 = *(const float4*)Ap;
    float4 b4 = *(const float4*)Bp;

    for (int k0 = 0; k0 < K; k0 += GBK) {
        As[lc + 0][lr] = a4.x; As[lc + 1][lr] = a4.y;
        As[lc + 2][lr] = a4.z; As[lc + 3][lr] = a4.w;
        Bs[lc + 0][lr] = b4.x; Bs[lc + 1][lr] = b4.y;
        Bs[lc + 2][lr] = b4.z; Bs[lc + 3][lr] = b4.w;
        __syncthreads();
        if (k0 + GBK < K) {
            a4 = *(const float4*)(Ap + k0 + GBK);
            b4 = *(const float4*)(Bp + k0 + GBK);
        }
#pragma unroll
        for (int kk = 0; kk < GBK; kk++) {
            float4 a0 = *(const float4*)&As[kk][ty * 8];
            float4 a1 = *(const float4*)&As[kk][ty * 8 + 4];
            ulonglong2 bp0 = *(const ulonglong2*)&Bs[kk][tx * 8];
            ulonglong2 bp1 = *(const ulonglong2*)&Bs[kk][tx * 8 + 4];
            u64 ad[8] = {dup2(a0.x), dup2(a0.y), dup2(a0.z), dup2(a0.w),
                         dup2(a1.x), dup2(a1.y), dup2(a1.z), dup2(a1.w)};
#pragma unroll
            for (int i = 0; i < 8; i++) {
                acc2[i][0] = fma2(ad[i], bp0.x, acc2[i][0]);
                acc2[i][1] = fma2(ad[i], bp0.y, acc2[i][1]);
                acc2[i][2] = fma2(ad[i], bp1.x, acc2[i][2]);
                acc2[i][3] = fma2(ad[i], bp1.y, acc2[i][3]);
            }
        }
        __syncthreads();
    }

#pragma unroll
    for (int i = 0; i < 8; i++) {
        long row = bm + ty * 8 + i;
#pragma unroll
        for (int j = 0; j < 4; j++) {
            int col = bn + tx * 8 + j * 2;
            float2 v = *(float2*)&acc2[i][j];
            v.x += bias[col];
            v.y += bias[col + 1];
            *(float2*)&C[row * N + col] = v;
        }
    }
}

// ---------------- persistent recurrence kernel ----------------
// 768 threads = 3 mats x 32 ks x 8 bq; warp = 4 ks x 8 bq.
// f32x2 packing over ROW PAIRS: weights stored unduplicated (32B per k for 8 rows),
// act scalars duplicated via mov. Per iter: 2 LDS.128 + 1 LDG.128 + 4 movs + 16 fma2.
struct RecSmem {
    float W[3][H][HB];          // [mat][k][row], unduplicated (96KB)
    u64   red[3][8][8][16];     // warp-reduced partials [m][ksgrp][bq][rp*4+b] (24KB)
    float res[3][HB][BATCH];
    float wb[3][HB];
    float br[HB], bi[HB], tb[HB];
};

__global__ void __launch_bounds__(BLOCK_R, 1) rec_kernel(
    const float* __restrict__ Wt_w,
    const float* __restrict__ Wr_b, const float* __restrict__ Wi_b,
    const float* __restrict__ Wt_b, const float* __restrict__ b_real,
    const float* __restrict__ b_imag, const float* __restrict__ tau_bias) {
    extern __shared__ char smem_raw[];
    RecSmem& sm = *reinterpret_cast<RecSmem*>(smem_raw);
    const int tid = threadIdx.x;
    const int hbase = blockIdx.x * HB;

    // ---- load weights into SMEM [mat][k][row] (resident for all 512 steps) ----
    for (int idx = tid; idx < 3 * HB * H; idx += BLOCK_R) {
        int m   = idx >> 13;
        int rem = idx & 8191;
        int r   = rem >> 10;
        int k   = rem & 1023;
        float w;
        if (m == 0)      w = g_Wr[(long)(hbase + r) * H + k];
        else if (m == 1) w = g_Wi[(long)(hbase + r) * H + k];
        else             w = Wt_w[(long)(hbase + r) * H + k];
        sm.W[m][k][r] = w;
    }
    if (tid < HB) {
        sm.wb[0][tid] = Wr_b[hbase + tid];
        sm.wb[1][tid] = Wi_b[hbase + tid];
        sm.wb[2][tid] = Wt_b[hbase + tid];
        sm.br[tid] = b_real[hbase + tid];
        sm.bi[tid] = b_imag[hbase + tid];
        sm.tb[tid] = tau_bias[hbase + tid];
    }
    __syncthreads();

    const int m  = tid >> 8;          // 0..2
    const int r5 = tid & 255;
    const int ks = r5 >> 3;           // 0..31
    const int bq = r5 & 7;            // 0..7

    const char* wk_base = (const char*)&sm.W[m][0][0];

    // cell state held in registers for the whole sequence (CTA-private)
    const int cb  = tid >> 3;         // batch (valid when tid < 256)
    const int chl = tid & 7;          // local h
    float zr = 0.0f, zi = 0.0f;

    int cur = 0;
    for (int t = 0; t < T_STEPS; t++) {
        // prefetch Ux for the epilogue (overlaps with matmul)
        float ux = 0.0f;
        if (tid < HB * BATCH)
            ux = __ldg(&g_Ux[((long)t * BATCH + cb) * H + hbase + chl]);

        const float* actp = g_act + (long)(cur * 3 + m) * (H * BATCH) + bq * 4;

        // acc[rp*4 + b] = packed (row 2rp, row 2rp+1) partial for batch (bq*4 + b)
        u64 acc[16];
#pragma unroll
        for (int j = 0; j < 16; j++) acc[j] = 0ull;

#pragma unroll 4
        for (int i = 0; i < 32; i++) {
            int k = ks + (i << 5);
            float4 a = __ldg((const float4*)(actp + k * BATCH));
            // 8 row-weights for this k: 32B contiguous -> 2x LDS.128
            ulonglong2 wA = *(const ulonglong2*)(wk_base + (size_t)k * (HB * 4));
            ulonglong2 wB = *(const ulonglong2*)(wk_base + (size_t)k * (HB * 4) + 16);
            u64 ad0 = dup2(a.x), ad1 = dup2(a.y), ad2 = dup2(a.z), ad3 = dup2(a.w);
            acc[0]  = fma2(ad0, wA.x, acc[0]);   // rows 0,1
            acc[1]  = fma2(ad1, wA.x, acc[1]);
            acc[2]  = fma2(ad2, wA.x, acc[2]);
            acc[3]  = fma2(ad3, wA.x, acc[3]);
            acc[4]  = fma2(ad0, wA.y, acc[4]);   // rows 2,3
            acc[5]  = fma2(ad1, wA.y, acc[5]);
            acc[6]  = fma2(ad2, wA.y, acc[6]);
            acc[7]  = fma2(ad3, wA.y, acc[7]);
            acc[8]  = fma2(ad0, wB.x, acc[8]);   // rows 4,5
            acc[9]  = fma2(ad1, wB.x, acc[9]);
            acc[10] = fma2(ad2, wB.x, acc[10]);
            acc[11] = fma2(ad3, wB.x, acc[11]);
            acc[12] = fma2(ad0, wB.y, acc[12]);  // rows 6,7
            acc[13] = fma2(ad1, wB.y, acc[13]);
            acc[14] = fma2(ad2, wB.y, acc[14]);
            acc[15] = fma2(ad3, wB.y, acc[15]);
        }

        // warp butterfly over the 4 kq lanes
#pragma unroll
        for (int j = 0; j < 16; j++) {
            u64 o = __shfl_xor_sync(0xffffffffu, acc[j], 8);
            acc[j] = add2(acc[j], o);
            o = __shfl_xor_sync(0xffffffffu, acc[j], 16);
            acc[j] = add2(acc[j], o);
        }
        if ((ks & 3) == 0) {
            int ksg = ks >> 2;
#pragma unroll
            for (int j = 0; j < 16; j++) sm.red[m][ksg][bq][j] = acc[j];
        }
        __syncthreads();

        // combine 8 k-groups: 384 combos, one per thread
        if (tid < 384) {
            int m2  = tid >> 7;
            int rem = tid & 127;
            int bq2 = rem >> 4;
            int j   = rem & 15;
            float2 s = *(float2*)&sm.red[m2][0][bq2][j];
#pragma unroll
            for (int g = 1; g < 8; g++) {
                float2 p = *(float2*)&sm.red[m2][g][bq2][j];
                s.x += p.x; s.y += p.y;
            }
            int rp = j >> 2;          // row pair
            int b  = bq2 * 4 + (j & 3);
            sm.res[m2][rp * 2 + 0][b] = s.x;
            sm.res[m2][rp * 2 + 1][b] = s.y;
        }
        __syncthreads();

        // elementwise update (state lives in registers)
        const int nxt = cur ^ 1;
        if (tid < HB * BATCH) {
            int b  = cb;
            int hl = chl;
            int h  = hbase + hl;
            float wr = sm.res[0][hl][b] + sm.wb[0][hl];
            float wi = sm.res[1][hl][b] + sm.wb[1][hl];
            float wt = sm.res[2][hl][b] + sm.wb[2][hl];
            float dr = -zr + wr + ux + sm.br[hl];
            float di = -zi + wi + ux + sm.bi[hl];
            float tau = 1.0f / (1.0f + expf(-wt)) + sm.tb[hl];
            tau = fminf(fmaxf(tau, 0.01f), 1.0f) + 1e-6f;
            dr = fminf(fmaxf(dr / tau, -10.0f), 10.0f);
            di = fminf(fmaxf(di / tau, -10.0f), 10.0f);
            zr = fminf(fmaxf(zr + DT_C * dr, -100.0f), 100.0f);
            zi = fminf(fmaxf(zi + DT_C * di, -100.0f), 100.0f);
            g_ZR[((long)t * BATCH + b) * H + h] = zr;
            float* ap = g_act + ((long)(nxt * 3) * H + h) * BATCH + b;
            ap[0 * H * BATCH] = tanhf(zr);
            ap[1 * H * BATCH] = tanhf(zi);
            ap[2 * H * BATCH] = sqrtf(zr * zr + zi * zi);
        }

        grid_barrier();
        cur ^= 1;
    }
}

// ---------------- launch ----------------
extern "C" void kernel_launch(void* const* d_in, const int* in_sizes, int n_in,
                              void* d_out, int out_size) {
    const float* x_seq    = (const float*)d_in[0];
    const float* Wr_w     = (const float*)d_in[1];
    const float* Wr_b     = (const float*)d_in[2];
    const float* Wi_w     = (const float*)d_in[3];
    const float* Wi_b     = (const float*)d_in[4];
    const float* U_w      = (const float*)d_in[5];
    const float* U_b      = (const float*)d_in[6];
    const float* Wt_w     = (const float*)d_in[7];
    const float* Wt_b     = (const float*)d_in[8];
    const float* b_real   = (const float*)d_in[9];
    const float* b_imag   = (const float*)d_in[10];
    const float* mask_r   = (const float*)d_in[11];
    const float* mask_i   = (const float*)d_in[12];
    const float* tau_bias = (const float*)d_in[13];
    const float* out_w    = (const float*)d_in[14];
    const float* out_b    = (const float*)d_in[15];
    float* y = (float*)d_out;

    float *p_Ux = nullptr, *p_ZR = nullptr;
    cudaGetSymbolAddress((void**)&p_Ux, g_Ux);
    cudaGetSymbolAddress((void**)&p_ZR, g_ZR);

    prep_kernel<<<(H * H + 255) / 256, 256>>>(Wr_w, mask_r, Wi_w, mask_i);
    init_kernel<<<(2 * 3 * H * BATCH + 255) / 256, 256>>>();

    {
        dim3 grid(H / GBN, (T_STEPS * BATCH) / GBM);
        sgemm_abt<<<grid, 256>>>(x_seq, U_w, U_b, p_Ux, T_STEPS * BATCH, H, DIN);
    }

    {
        int smem = (int)sizeof(RecSmem);
        cudaFuncSetAttribute(rec_kernel, cudaFuncAttributeMaxDynamicSharedMemorySize, smem);
        rec_kernel<<<GRID_R, BLOCK_R, smem>>>(Wt_w, Wr_b, Wi_b, Wt_b, b_real, b_imag, tau_bias);
    }

    {
        dim3 grid(H / GBN, (T_STEPS * BATCH) / GBM);
        sgemm_abt<<<grid, 256>>>(p_ZR, out_w, out_b, y, T_STEPS * BATCH, H, H);
    }
}